// round 7
// baseline (speedup 1.0000x reference)
#include <cuda_runtime.h>
#include <cstdint>
#include <cstddef>

// ---------------- problem constants ----------------
#define T_FRAMES 48
#define D_IN     2048
#define H_GRU    512
#define G3H      1536      // 3*H
#define C2H      1024      // 2*H
#define NSEQ     320       // 64 main + 256 support
#define MAIN_ROWS 3072     // 64*48
#define M_ALL    15360     // 320*48
#define NCONV    7168      // 512*(2+3+4+5)
#define FEATD    5120
#define NB       64
#define NS       4

// ---------------- device scratch ----------------
__device__ float    g_xg [(size_t)M_ALL * 2 * G3H];
__device__ float    g_h  [2 * NSEQ * H_GRU];
__device__ float    g_hg [2 * NSEQ * G3H];
__device__ float    g_gru[(size_t)NSEQ * T_FRAMES * C2H];
__device__ float    g_Bc [(size_t)NCONV * C2H];
__device__ float    g_P  [(size_t)M_ALL * NCONV];
__device__ float    g_feat[(size_t)NSEQ * FEATD];
__device__ float    g_q  [NB * 512];
__device__ float    g_k  [NB * NS * 512];
__device__ uint32_t g_Whi[2 * G3H * H_GRU];   // tf32 hi of W_hh (both dirs), packed once
__device__ uint32_t g_Wlo[2 * G3H * H_GRU];   // tf32 lo residual

// ---------------- tf32 helpers ----------------
__device__ __forceinline__ uint32_t f2tf32(float f) {
    uint32_t u;
    asm("cvt.rna.tf32.f32 %0, %1;" : "=r"(u) : "f"(f));
    return u;
}
__device__ __forceinline__ void mma_tf32(float c[4], uint32_t a0, uint32_t a1,
                                         uint32_t a2, uint32_t a3,
                                         uint32_t b0, uint32_t b1) {
    asm volatile(
        "mma.sync.aligned.m16n8k8.row.col.f32.tf32.tf32.f32 "
        "{%0,%1,%2,%3}, {%4,%5,%6,%7}, {%8,%9}, {%0,%1,%2,%3};"
        : "+f"(c[0]), "+f"(c[1]), "+f"(c[2]), "+f"(c[3])
        : "r"(a0), "r"(a1), "r"(a2), "r"(a3), "r"(b0), "r"(b1));
}

// ---------------- tf32 tensor-core NT GEMM, double-buffered smem ----------------
// C[m][n] = bias(n) + sum_k A(m)[k] * B(n)[k]
// REQUIRES: M%128==0, N%128==0, K%16==0, msplit/nsplit multiples of 128.
// BK=16 so two stages fit in 48KB static smem; ONE __syncthreads per K-step.
__global__ void __launch_bounds__(256)
gemm_tf32(int M, int N, int K,
          const float* __restrict__ A0, const float* __restrict__ A1, int msplit, int lda,
          const float* __restrict__ B0, const float* __restrict__ B1, int nsplit, int ldb,
          const float* __restrict__ bias0, const float* __restrict__ bias1,
          float* __restrict__ C, int ldc)
{
    constexpr int BM = 128, BN = 128, BK = 16, PAD = 4;
    __shared__ uint32_t As[2][BM][BK + PAD];   // 2*128*20*4 = 20480 B
    __shared__ uint32_t Bs[2][BN][BK + PAD];   // + 20480 B = 40 KB total

    const int tid  = threadIdx.x;
    const int lane = tid & 31;
    const int warp = tid >> 5;
    const int wm0 = (warp & 1) * 64;
    const int wn0 = (warp >> 1) * 32;
    const int bm = blockIdx.y * BM;
    const int bn = blockIdx.x * BN;
    const int g  = lane >> 2;
    const int tg = lane & 3;

    float acc[4][4][4];
    #pragma unroll
    for (int i = 0; i < 4; i++)
        #pragma unroll
        for (int j = 0; j < 4; j++)
            #pragma unroll
            for (int r = 0; r < 4; r++) acc[i][j][r] = 0.f;

    // staging map: 512 float4 per matrix per tile over 256 threads = 2 each
    // p = tid + i*256; row = p >> 2 (BK/4 = 4 vec4 per row); cv = (p & 3) * 4
    float4 pa[2], pb[2];

    // prologue: load + commit k0 = 0 into buffer 0
    #pragma unroll
    for (int i = 0; i < 2; i++) {
        int p = tid + i * 256, row = p >> 2, cv = (p & 3) * 4;
        int m = bm + row;
        const float* a = (m < msplit) ? (A0 + (size_t)m * lda)
                                      : (A1 + (size_t)(m - msplit) * lda);
        pa[i] = *(const float4*)(a + cv);
        int n = bn + row;
        const float* b = (n < nsplit) ? (B0 + (size_t)n * ldb)
                                      : (B1 + (size_t)(n - nsplit) * ldb);
        pb[i] = *(const float4*)(b + cv);
    }
    #pragma unroll
    for (int i = 0; i < 2; i++) {
        int p = tid + i * 256, row = p >> 2, cv = (p & 3) * 4;
        As[0][row][cv+0] = f2tf32(pa[i].x); As[0][row][cv+1] = f2tf32(pa[i].y);
        As[0][row][cv+2] = f2tf32(pa[i].z); As[0][row][cv+3] = f2tf32(pa[i].w);
        Bs[0][row][cv+0] = f2tf32(pb[i].x); Bs[0][row][cv+1] = f2tf32(pb[i].y);
        Bs[0][row][cv+2] = f2tf32(pb[i].z); Bs[0][row][cv+3] = f2tf32(pb[i].w);
    }
    __syncthreads();

    int buf = 0;
    for (int k0 = 0; k0 < K; k0 += BK) {
        const bool has_next = (k0 + BK < K);
        // issue next tile's LDGs first — latency hidden by the MMA phase below
        if (has_next) {
            #pragma unroll
            for (int i = 0; i < 2; i++) {
                int p = tid + i * 256, row = p >> 2, cv = (p & 3) * 4;
                int m = bm + row;
                const float* a = (m < msplit) ? (A0 + (size_t)m * lda)
                                              : (A1 + (size_t)(m - msplit) * lda);
                pa[i] = *(const float4*)(a + k0 + BK + cv);
                int n = bn + row;
                const float* b = (n < nsplit) ? (B0 + (size_t)n * ldb)
                                              : (B1 + (size_t)(n - nsplit) * ldb);
                pb[i] = *(const float4*)(b + k0 + BK + cv);
            }
        }
        // compute on current buffer: 2 x k8 steps
        #pragma unroll
        for (int kk = 0; kk < 2; kk++) {
            const int kb = kk * 8;
            uint32_t af[4][4];
            #pragma unroll
            for (int i = 0; i < 4; i++) {
                int r0 = wm0 + i * 16 + g;
                af[i][0] = As[buf][r0    ][kb + tg    ];
                af[i][1] = As[buf][r0 + 8][kb + tg    ];
                af[i][2] = As[buf][r0    ][kb + tg + 4];
                af[i][3] = As[buf][r0 + 8][kb + tg + 4];
            }
            uint32_t bf[4][2];
            #pragma unroll
            for (int j = 0; j < 4; j++) {
                int n0 = wn0 + j * 8 + g;
                bf[j][0] = Bs[buf][n0][kb + tg    ];
                bf[j][1] = Bs[buf][n0][kb + tg + 4];
            }
            #pragma unroll
            for (int i = 0; i < 4; i++)
                #pragma unroll
                for (int j = 0; j < 4; j++)
                    mma_tf32(acc[i][j], af[i][0], af[i][1], af[i][2], af[i][3],
                             bf[j][0], bf[j][1]);
        }
        // commit next tile into the other buffer; one barrier per iteration
        if (has_next) {
            int nb_ = buf ^ 1;
            #pragma unroll
            for (int i = 0; i < 2; i++) {
                int p = tid + i * 256, row = p >> 2, cv = (p & 3) * 4;
                As[nb_][row][cv+0] = f2tf32(pa[i].x); As[nb_][row][cv+1] = f2tf32(pa[i].y);
                As[nb_][row][cv+2] = f2tf32(pa[i].z); As[nb_][row][cv+3] = f2tf32(pa[i].w);
                Bs[nb_][row][cv+0] = f2tf32(pb[i].x); Bs[nb_][row][cv+1] = f2tf32(pb[i].y);
                Bs[nb_][row][cv+2] = f2tf32(pb[i].z); Bs[nb_][row][cv+3] = f2tf32(pb[i].w);
            }
            __syncthreads();
            buf = nb_;
        }
    }

    #pragma unroll
    for (int i = 0; i < 4; i++) {
        int row = bm + wm0 + i * 16 + g;
        #pragma unroll
        for (int j = 0; j < 4; j++) {
            int col = bn + wn0 + j * 8 + 2 * tg;
            float bv0 = 0.f, bv1 = 0.f;
            if (bias0) {
                const float* bp = (col < nsplit) ? (bias0 + col) : (bias1 + col - nsplit);
                bv0 = bp[0]; bv1 = bp[1];
            }
            float2 v0 = make_float2(acc[i][j][0] + bv0, acc[i][j][1] + bv1);
            float2 v1 = make_float2(acc[i][j][2] + bv0, acc[i][j][3] + bv1);
            *(float2*)(C + (size_t)row * ldc + col)       = v0;
            *(float2*)(C + (size_t)(row + 8) * ldc + col) = v1;
        }
    }
}

// ---------------- pack W_hh into tf32 hi/lo (once; reused 48x) ----------------
__global__ void pack_whh(const float* __restrict__ Wf, const float* __restrict__ Wb,
                         uint32_t* __restrict__ Whi, uint32_t* __restrict__ Wlo)
{
    int idx = blockIdx.x * blockDim.x + threadIdx.x;
    if (idx >= 2 * G3H * H_GRU) return;
    float v = (idx < G3H * H_GRU) ? Wf[idx] : Wb[idx - G3H * H_GRU];
    uint32_t hi = f2tf32(v);
    Whi[idx] = hi;
    Wlo[idx] = f2tf32(v - __uint_as_float(hi));
}

// ---------------- GRU hh GEMM: 3xTF32, round-6 proven version ----------------
__global__ void __launch_bounds__(256)
gemm_hh_tf32(const float* __restrict__ h,
             const uint32_t* __restrict__ Whi, const uint32_t* __restrict__ Wlo,
             const float* __restrict__ bf_, const float* __restrict__ bb_,
             float* __restrict__ hg)
{
    constexpr int BK = 32, PAD = 4;
    __shared__ uint32_t As_hi[64][BK + PAD];
    __shared__ uint32_t As_lo[64][BK + PAD];
    __shared__ uint32_t Bs_hi[64][BK + PAD];
    __shared__ uint32_t Bs_lo[64][BK + PAD];

    const int tid  = threadIdx.x;
    const int lane = tid & 31;
    const int warp = tid >> 5;
    const int wm0 = (warp & 1) * 32;
    const int wn0 = (warp >> 1) * 16;
    const int g  = lane >> 2;
    const int tg = lane & 3;

    const int dir = blockIdx.z;
    const int m0 = blockIdx.y * 64;
    const int n0t = blockIdx.x * 64;
    const float* A = h + (size_t)dir * NSEQ * H_GRU;
    const uint32_t* Bh = Whi + (size_t)dir * G3H * H_GRU;
    const uint32_t* Bl = Wlo + (size_t)dir * G3H * H_GRU;
    const float* bias = dir ? bb_ : bf_;
    float* C = hg + (size_t)dir * NSEQ * G3H;

    float acc[2][2][4];
    #pragma unroll
    for (int i = 0; i < 2; i++)
        #pragma unroll
        for (int j = 0; j < 2; j++)
            #pragma unroll
            for (int r = 0; r < 4; r++) acc[i][j][r] = 0.f;

    float4 pa[2];
    uint4  pbh[2], pbl[2];
    #pragma unroll
    for (int i = 0; i < 2; i++) {
        int p = tid + i * 256, row = p >> 3, kc = (p & 7) * 4;
        pa[i]  = *(const float4*)(A  + (size_t)(m0 + row) * H_GRU + kc);
        pbh[i] = *(const uint4*)(Bh + (size_t)(n0t + row) * H_GRU + kc);
        pbl[i] = *(const uint4*)(Bl + (size_t)(n0t + row) * H_GRU + kc);
    }

    for (int k0 = 0; k0 < H_GRU; k0 += BK) {
        #pragma unroll
        for (int i = 0; i < 2; i++) {
            int p = tid + i * 256, row = p >> 3, kc = (p & 7) * 4;
            float av[4] = {pa[i].x, pa[i].y, pa[i].z, pa[i].w};
            #pragma unroll
            for (int e = 0; e < 4; e++) {
                uint32_t ah = f2tf32(av[e]);
                As_hi[row][kc + e] = ah;
                As_lo[row][kc + e] = f2tf32(av[e] - __uint_as_float(ah));
            }
            Bs_hi[row][kc+0] = pbh[i].x; Bs_hi[row][kc+1] = pbh[i].y;
            Bs_hi[row][kc+2] = pbh[i].z; Bs_hi[row][kc+3] = pbh[i].w;
            Bs_lo[row][kc+0] = pbl[i].x; Bs_lo[row][kc+1] = pbl[i].y;
            Bs_lo[row][kc+2] = pbl[i].z; Bs_lo[row][kc+3] = pbl[i].w;
        }
        __syncthreads();
        if (k0 + BK < H_GRU) {
            #pragma unroll
            for (int i = 0; i < 2; i++) {
                int p = tid + i * 256, row = p >> 3, kc = (p & 7) * 4;
                pa[i]  = *(const float4*)(A  + (size_t)(m0 + row) * H_GRU + k0 + BK + kc);
                pbh[i] = *(const uint4*)(Bh + (size_t)(n0t + row) * H_GRU + k0 + BK + kc);
                pbl[i] = *(const uint4*)(Bl + (size_t)(n0t + row) * H_GRU + k0 + BK + kc);
            }
        }
        #pragma unroll
        for (int kk = 0; kk < 4; kk++) {
            const int kb = kk * 8;
            uint32_t ah[2][4], al[2][4], bh[2][2], bl[2][2];
            #pragma unroll
            for (int i = 0; i < 2; i++) {
                int r0 = wm0 + i * 16 + g;
                ah[i][0] = As_hi[r0    ][kb + tg    ];
                ah[i][1] = As_hi[r0 + 8][kb + tg    ];
                ah[i][2] = As_hi[r0    ][kb + tg + 4];
                ah[i][3] = As_hi[r0 + 8][kb + tg + 4];
                al[i][0] = As_lo[r0    ][kb + tg    ];
                al[i][1] = As_lo[r0 + 8][kb + tg    ];
                al[i][2] = As_lo[r0    ][kb + tg + 4];
                al[i][3] = As_lo[r0 + 8][kb + tg + 4];
            }
            #pragma unroll
            for (int j = 0; j < 2; j++) {
                int nn = wn0 + j * 8 + g;
                bh[j][0] = Bs_hi[nn][kb + tg    ];
                bh[j][1] = Bs_hi[nn][kb + tg + 4];
                bl[j][0] = Bs_lo[nn][kb + tg    ];
                bl[j][1] = Bs_lo[nn][kb + tg + 4];
            }
            #pragma unroll
            for (int i = 0; i < 2; i++)
                #pragma unroll
                for (int j = 0; j < 2; j++) {
                    mma_tf32(acc[i][j], al[i][0], al[i][1], al[i][2], al[i][3],
                             bh[j][0], bh[j][1]);
                    mma_tf32(acc[i][j], ah[i][0], ah[i][1], ah[i][2], ah[i][3],
                             bl[j][0], bl[j][1]);
                    mma_tf32(acc[i][j], ah[i][0], ah[i][1], ah[i][2], ah[i][3],
                             bh[j][0], bh[j][1]);
                }
        }
        __syncthreads();
    }

    #pragma unroll
    for (int i = 0; i < 2; i++) {
        int row = m0 + wm0 + i * 16 + g;
        #pragma unroll
        for (int j = 0; j < 2; j++) {
            int col = n0t + wn0 + j * 8 + 2 * tg;
            float bv0 = bias[col], bv1 = bias[col + 1];
            float2 v0 = make_float2(acc[i][j][0] + bv0, acc[i][j][1] + bv1);
            float2 v1 = make_float2(acc[i][j][2] + bv0, acc[i][j][3] + bv1);
            *(float2*)(C + (size_t)row * G3H + col)       = v0;
            *(float2*)(C + (size_t)(row + 8) * G3H + col) = v1;
        }
    }
}

// ---------------- fp32 SIMT NT GEMM (small GEMMs) ----------------
template<int BM, int BN, int BK, int TM, int TN>
__global__ void __launch_bounds__((BM/TM)*(BN/TN))
gemm_nt(int M, int N, int K,
        const float* __restrict__ A0, const float* __restrict__ A1, int msplit, int lda,
        const float* __restrict__ B, int ldb,
        const float* __restrict__ bias,
        float* __restrict__ C, int ldc)
{
    constexpr int THREADS = (BM/TM)*(BN/TN);
    constexpr int KV = BK/4;
    __shared__ float Ast[BK][BM];
    __shared__ float Bst[BK][BN];
    const int tid = threadIdx.x;
    const int bm = blockIdx.y * BM;
    const int bn = blockIdx.x * BN;
    const int tx = tid % (BN/TN);
    const int ty = tid / (BN/TN);

    float acc[TM][TN];
    #pragma unroll
    for (int i = 0; i < TM; i++)
        #pragma unroll
        for (int j = 0; j < TN; j++) acc[i][j] = 0.f;

    for (int k0 = 0; k0 < K; k0 += BK) {
        #pragma unroll
        for (int p = tid; p < BM*KV; p += THREADS) {
            int row = p / KV;
            int kc  = (p % KV) * 4;
            int m = bm + row;
            float4 v = make_float4(0.f, 0.f, 0.f, 0.f);
            if (m < M) {
                const float* a = (m < msplit) ? (A0 + (size_t)m * lda)
                                              : (A1 + (size_t)(m - msplit) * lda);
                v = *(const float4*)(a + k0 + kc);
            }
            Ast[kc+0][row] = v.x; Ast[kc+1][row] = v.y;
            Ast[kc+2][row] = v.z; Ast[kc+3][row] = v.w;
        }
        #pragma unroll
        for (int p = tid; p < BN*KV; p += THREADS) {
            int row = p / KV;
            int kc  = (p % KV) * 4;
            int n = bn + row;
            float4 v = make_float4(0.f, 0.f, 0.f, 0.f);
            if (n < N) v = *(const float4*)(B + (size_t)n * ldb + k0 + kc);
            Bst[kc+0][row] = v.x; Bst[kc+1][row] = v.y;
            Bst[kc+2][row] = v.z; Bst[kc+3][row] = v.w;
        }
        __syncthreads();
        #pragma unroll
        for (int kk = 0; kk < BK; kk++) {
            float ra[TM], rb[TN];
            #pragma unroll
            for (int i = 0; i < TM; i += 4)
                *(float4*)&ra[i] = *(const float4*)&Ast[kk][ty*TM + i];
            #pragma unroll
            for (int j = 0; j < TN; j += 4)
                *(float4*)&rb[j] = *(const float4*)&Bst[kk][tx*TN + j];
            #pragma unroll
            for (int i = 0; i < TM; i++)
                #pragma unroll
                for (int j = 0; j < TN; j++)
                    acc[i][j] = fmaf(ra[i], rb[j], acc[i][j]);
        }
        __syncthreads();
    }
    #pragma unroll
    for (int i = 0; i < TM; i++) {
        int m = bm + ty*TM + i;
        if (m >= M) continue;
        #pragma unroll
        for (int j = 0; j < TN; j += 4) {
            int n = bn + tx*TN + j;
            float4 v;
            v.x = acc[i][j+0]; v.y = acc[i][j+1];
            v.z = acc[i][j+2]; v.w = acc[i][j+3];
            if (bias) { v.x += bias[n]; v.y += bias[n+1]; v.z += bias[n+2]; v.w += bias[n+3]; }
            *(float4*)(C + (size_t)m * ldc + n) = v;
        }
    }
}

// ---------------- misc kernels ----------------
__global__ void zero_kernel(float* p, int n) {
    int i = blockIdx.x * blockDim.x + threadIdx.x;
    if (i < n) p[i] = 0.f;
}

__global__ void gru_step(const float* __restrict__ xg,
                         const float* __restrict__ hg_all,
                         float* __restrict__ h_all,
                         const float* __restrict__ vmask, const float* __restrict__ smask,
                         float* __restrict__ gru, int s)
{
    int idx = blockIdx.x * blockDim.x + threadIdx.x;
    if (idx >= 2 * NSEQ * (H_GRU / 4)) return;
    const int JW = H_GRU / 4;
    int dir = idx / (NSEQ * JW);
    int r = idx - dir * NSEQ * JW;
    int n = r / JW;
    int j4 = (r - n * JW) * 4;
    int t = dir ? (T_FRAMES - 1 - s) : s;

    size_t xo = ((size_t)n * T_FRAMES + t) * (2 * G3H) + (size_t)dir * G3H;
    float4 xr = *(const float4*)(xg + xo + j4);
    float4 xz = *(const float4*)(xg + xo + H_GRU + j4);
    float4 xn = *(const float4*)(xg + xo + 2*H_GRU + j4);

    const float* hgp = hg_all + (size_t)dir * NSEQ * G3H + (size_t)n * G3H;
    float4 hr = *(const float4*)(hgp + j4);
    float4 hz = *(const float4*)(hgp + H_GRU + j4);
    float4 hn = *(const float4*)(hgp + 2*H_GRU + j4);

    float* hp = h_all + (size_t)dir * NSEQ * H_GRU + (size_t)n * H_GRU + j4;
    float4 hold = *(float4*)hp;

    float mval = (n < NB) ? vmask[n * T_FRAMES + t]
                          : smask[(n - NB) * T_FRAMES + t];

    float xrv[4] = {xr.x, xr.y, xr.z, xr.w};
    float xzv[4] = {xz.x, xz.y, xz.z, xz.w};
    float xnv[4] = {xn.x, xn.y, xn.z, xn.w};
    float hrv[4] = {hr.x, hr.y, hr.z, hr.w};
    float hzv[4] = {hz.x, hz.y, hz.z, hz.w};
    float hnv[4] = {hn.x, hn.y, hn.z, hn.w};
    float hov[4] = {hold.x, hold.y, hold.z, hold.w};
    float outv[4], gw[4];
    #pragma unroll
    for (int e = 0; e < 4; e++) {
        float rg = 1.f / (1.f + __expf(-(xrv[e] + hrv[e])));
        float zg = 1.f / (1.f + __expf(-(xzv[e] + hzv[e])));
        float ng = __tanhf(xnv[e] + rg * hnv[e]);
        float hv = (1.f - zg) * ng + zg * hov[e];
        outv[e] = hv;
        gw[e] = hv * mval;
    }
    *(float4*)hp = make_float4(outv[0], outv[1], outv[2], outv[3]);
    *(float4*)(gru + ((size_t)n * T_FRAMES + t) * C2H + dir * H_GRU + j4) =
        make_float4(gw[0], gw[1], gw[2], gw[3]);
}

__global__ void pool_origin(const float* __restrict__ gru,
                            const int* __restrict__ len, const int* __restrict__ slen,
                            const float* __restrict__ vorig, const float* __restrict__ sorig,
                            float* __restrict__ feat)
{
    int idx = blockIdx.x * blockDim.x + threadIdx.x;
    if (idx >= NSEQ * (C2H + D_IN)) return;
    int n = idx / (C2H + D_IN);
    int c = idx - n * (C2H + D_IN);
    if (c < C2H) {
        const float* g = gru + (size_t)n * T_FRAMES * C2H + c;
        float s = 0.f;
        #pragma unroll
        for (int t = 0; t < T_FRAMES; t++) s += g[(size_t)t * C2H];
        int L = (n < NB) ? len[n] : slen[n - NB];
        feat[(size_t)n * FEATD + c] = s / (float)L;
    } else {
        int cc = c - C2H;
        float v = (n < NB) ? vorig[(size_t)n * D_IN + cc]
                           : sorig[(size_t)(n - NB) * D_IN + cc];
        feat[(size_t)n * FEATD + (C2H + 4*512) + cc] = v;
    }
}

__global__ void pack_conv(const float* __restrict__ w2, const float* __restrict__ w3,
                          const float* __restrict__ w4, const float* __restrict__ w5,
                          float* __restrict__ Bc)
{
    int idx = blockIdx.x * blockDim.x + threadIdx.x;
    if (idx >= NCONV * C2H) return;
    int col = idx / C2H;
    int c = idx - col * C2H;
    int w, k, i; const float* src;
    if (col < 1024)      { w = 2; src = w2; int r = col;        k = r / 2; i = r - k*2; }
    else if (col < 2560) { w = 3; src = w3; int r = col - 1024; k = r / 3; i = r - k*3; }
    else if (col < 4608) { w = 4; src = w4; int r = col - 2560; k = r / 4; i = r - k*4; }
    else                 { w = 5; src = w5; int r = col - 4608; k = r / 5; i = r - k*5; }
    Bc[(size_t)col * C2H + c] = src[((size_t)k * C2H + c) * w + i];
}

__global__ void conv_reduce(const float* __restrict__ P,
                            const float* __restrict__ cb2, const float* __restrict__ cb3,
                            const float* __restrict__ cb4, const float* __restrict__ cb5,
                            float* __restrict__ feat)
{
    int idx = blockIdx.x * blockDim.x + threadIdx.x;
    if (idx >= NSEQ * 2048) return;
    int n = idx / 2048;
    int c = idx - n * 2048;
    int widx = c >> 9;
    int k = c & 511;
    int w = widx + 2;
    int base = (widx == 0) ? 0 : (widx == 1) ? 1024 : (widx == 2) ? 2560 : 4608;
    const float* cb = (widx == 0) ? cb2 : (widx == 1) ? cb3 : (widx == 2) ? cb4 : cb5;
    float bb = cb[k];
    const float* Pn = P + (size_t)n * T_FRAMES * NCONV + base + k * w;
    float best = 0.f;
    for (int tau = 0; tau < T_FRAMES + w - 1; tau++) {
        float y = bb;
        for (int i = 0; i < w; i++) {
            int t = tau + i - (w - 1);
            if (t >= 0 && t < T_FRAMES) y += Pn[(size_t)t * NCONV + i];
        }
        best = fmaxf(best, y);
    }
    feat[(size_t)n * FEATD + C2H + c] = best;
}

__global__ void attn_out(const float* __restrict__ feat, const float* __restrict__ q,
                         const float* __restrict__ kf, float* __restrict__ out)
{
    int b = blockIdx.x;
    int tid = threadIdx.x;
    __shared__ float logits[NS];
    __shared__ float wgt[NS];
    if (tid < 32 * NS) {
        int s = tid >> 5, lane = tid & 31;
        const float* kk = kf + (size_t)(b * NS + s) * 512;
        const float* qq = q + (size_t)b * 512;
        float sum = 0.f;
        for (int h = lane; h < 512; h += 32) sum += kk[h] * qq[h];
        #pragma unroll
        for (int o = 16; o; o >>= 1) sum += __shfl_down_sync(0xffffffffu, sum, o);
        if (lane == 0) logits[s] = sum;
    }
    __syncthreads();
    if (tid == 0) {
        float mx = fmaxf(fmaxf(logits[0], logits[1]), fmaxf(logits[2], logits[3]));
        float e0 = expf(logits[0]-mx), e1 = expf(logits[1]-mx);
        float e2 = expf(logits[2]-mx), e3 = expf(logits[3]-mx);
        float se = e0 + e1 + e2 + e3;
        wgt[0] = e0/se; wgt[1] = e1/se; wgt[2] = e2/se; wgt[3] = e3/se;
    }
    __syncthreads();
    float w0 = wgt[0], w1 = wgt[1], w2 = wgt[2], w3 = wgt[3];
    const float* f0 = feat + (size_t)b * FEATD;
    const float* s0 = feat + (size_t)(NB + b * NS) * FEATD;
    for (int f = tid; f < FEATD; f += blockDim.x) {
        out[(size_t)b * FEATD + f] = f0[f]
            + w0 * s0[f] + w1 * s0[FEATD + f]
            + w2 * s0[2*(size_t)FEATD + f] + w3 * s0[3*(size_t)FEATD + f];
    }
}

// ---------------- launch ----------------
extern "C" void kernel_launch(void* const* d_in, const int* in_sizes, int n_in,
                              void* d_out, int out_size)
{
    const float* videos   = (const float*)d_in[0];
    const float* vorigin  = (const float*)d_in[1];
    const int*   lengths  = (const int*)  d_in[2];
    const float* vmask    = (const float*)d_in[3];
    const float* svideos  = (const float*)d_in[4];
    const float* sorigin  = (const float*)d_in[5];
    const int*   slengths = (const int*)  d_in[6];
    const float* smask    = (const float*)d_in[7];
    const float* W_ih_f = (const float*)d_in[10];
    const float* W_hh_f = (const float*)d_in[11];
    const float* b_ih_f = (const float*)d_in[12];
    const float* b_hh_f = (const float*)d_in[13];
    const float* W_ih_b = (const float*)d_in[14];
    const float* W_hh_b = (const float*)d_in[15];
    const float* b_ih_b = (const float*)d_in[16];
    const float* b_hh_b = (const float*)d_in[17];
    const float* cw2 = (const float*)d_in[18]; const float* cb2 = (const float*)d_in[19];
    const float* cw3 = (const float*)d_in[20]; const float* cb3 = (const float*)d_in[21];
    const float* cw4 = (const float*)d_in[22]; const float* cb4 = (const float*)d_in[23];
    const float* cw5 = (const float*)d_in[24]; const float* cb5 = (const float*)d_in[25];
    const float* Wk = (const float*)d_in[26]; const float* bk = (const float*)d_in[27];
    const float* Wq = (const float*)d_in[28]; const float* bq = (const float*)d_in[29];
    float* out = (float*)d_out;

    float *p_xg, *p_h, *p_hg, *p_gru, *p_Bc, *p_P, *p_feat, *p_q, *p_k;
    uint32_t *p_Whi, *p_Wlo;
    cudaGetSymbolAddress((void**)&p_xg,   g_xg);
    cudaGetSymbolAddress((void**)&p_h,    g_h);
    cudaGetSymbolAddress((void**)&p_hg,   g_hg);
    cudaGetSymbolAddress((void**)&p_gru,  g_gru);
    cudaGetSymbolAddress((void**)&p_Bc,   g_Bc);
    cudaGetSymbolAddress((void**)&p_P,    g_P);
    cudaGetSymbolAddress((void**)&p_feat, g_feat);
    cudaGetSymbolAddress((void**)&p_q,    g_q);
    cudaGetSymbolAddress((void**)&p_k,    g_k);
    cudaGetSymbolAddress((void**)&p_Whi,  g_Whi);
    cudaGetSymbolAddress((void**)&p_Wlo,  g_Wlo);

    zero_kernel<<<(2*NSEQ*H_GRU + 255)/256, 256>>>(p_h, 2*NSEQ*H_GRU);
    pack_whh<<<(2*G3H*H_GRU + 255)/256, 256>>>(W_hh_f, W_hh_b, p_Whi, p_Wlo);

    // fused fwd+bwd input projection: [15360 x 2048] x [3072 x 2048]^T (tf32, dbl-buf)
    gemm_tf32<<<dim3(2*G3H/128, M_ALL/128), 256>>>(M_ALL, 2*G3H, D_IN,
        videos, svideos, MAIN_ROWS, D_IN,
        W_ih_f, W_ih_b, G3H, D_IN,
        b_ih_f, b_ih_b, p_xg, 2*G3H);

    pack_conv<<<(NCONV*C2H + 255)/256, 256>>>(cw2, cw3, cw4, cw5, p_Bc);

    // GRU recurrence (round-6 proven)
    for (int s = 0; s < T_FRAMES; s++) {
        gemm_hh_tf32<<<dim3(G3H/64, NSEQ/64, 2), 256>>>(
            p_h, p_Whi, p_Wlo, b_hh_f, b_hh_b, p_hg);
        gru_step<<<(2*NSEQ*(H_GRU/4) + 255)/256, 256>>>(
            p_xg, p_hg, p_h, vmask, smask, p_gru, s);
    }

    pool_origin<<<(NSEQ*(C2H + D_IN) + 255)/256, 256>>>(
        p_gru, lengths, slengths, vorigin, sorigin, p_feat);

    // conv-as-GEMM: [15360 x 1024] x [7168 x 1024]^T (tf32, dbl-buf)
    gemm_tf32<<<dim3(NCONV/128, M_ALL/128), 256>>>(M_ALL, NCONV, C2H,
        p_gru, p_gru, M_ALL, C2H,
        p_Bc, p_Bc, NCONV, C2H,
        nullptr, nullptr, p_P, NCONV);
    conv_reduce<<<(NSEQ*2048 + 255)/256, 256>>>(p_P, cb2, cb3, cb4, cb5, p_feat);

    // query / key projections (fp32)
    gemm_nt<64,64,16,4,4><<<dim3(512/64, 1), 256>>>(NB, 512, FEATD,
        p_feat, p_feat, NB, FEATD, Wq, FEATD, bq, p_q, 512);
    gemm_nt<64,64,16,4,4><<<dim3(512/64, 4), 256>>>(NB*NS, 512, FEATD,
        p_feat + (size_t)NB*FEATD, p_feat + (size_t)NB*FEATD, NB*NS, FEATD,
        Wk, FEATD, bk, p_k, 512);

    attn_out<<<NB, 256>>>(p_feat, p_q, p_k, out);
}

// round 8
// speedup vs baseline: 1.1701x; 1.1701x over previous
#include <cuda_runtime.h>
#include <cstdint>
#include <cstddef>

// ---------------- problem constants ----------------
#define T_FRAMES 48
#define D_IN     2048
#define H_GRU    512
#define G3H      1536      // 3*H
#define C2H      1024      // 2*H
#define NSEQ     320       // 64 main + 256 support
#define MAIN_ROWS 3072     // 64*48
#define M_ALL    15360     // 320*48
#define NCONV    7168      // 512*(2+3+4+5)
#define FEATD    5120
#define NB       64
#define NS       4
#define KSPLIT   2         // split-K factor for hh GEMM (K=512 -> 2 x 256)

// ---------------- device scratch ----------------
__device__ float    g_xg [(size_t)M_ALL * 2 * G3H];
__device__ float    g_h  [2 * NSEQ * H_GRU];
__device__ float    g_hg [KSPLIT * 2 * NSEQ * G3H];       // [ks][dir][n][g] partials
__device__ float    g_gru[(size_t)NSEQ * T_FRAMES * C2H];
__device__ float    g_Bc [(size_t)NCONV * C2H];
__device__ float    g_P  [(size_t)M_ALL * NCONV];
__device__ float    g_feat[(size_t)NSEQ * FEATD];
__device__ float    g_q  [NB * 512];
__device__ float    g_k  [NB * NS * 512];
__device__ uint32_t g_Whi[2 * G3H * H_GRU];   // tf32 hi of W_hh (both dirs), packed once
__device__ uint32_t g_Wlo[2 * G3H * H_GRU];   // tf32 lo residual

// ---------------- tf32 helpers ----------------
__device__ __forceinline__ uint32_t f2tf32(float f) {
    uint32_t u;
    asm("cvt.rna.tf32.f32 %0, %1;" : "=r"(u) : "f"(f));
    return u;
}
__device__ __forceinline__ void mma_tf32(float c[4], uint32_t a0, uint32_t a1,
                                         uint32_t a2, uint32_t a3,
                                         uint32_t b0, uint32_t b1) {
    asm volatile(
        "mma.sync.aligned.m16n8k8.row.col.f32.tf32.tf32.f32 "
        "{%0,%1,%2,%3}, {%4,%5,%6,%7}, {%8,%9}, {%0,%1,%2,%3};"
        : "+f"(c[0]), "+f"(c[1]), "+f"(c[2]), "+f"(c[3])
        : "r"(a0), "r"(a1), "r"(a2), "r"(a3), "r"(b0), "r"(b1));
}

// ---------------- tf32 tensor-core NT GEMM (round-2/6 proven, single-buffer) ----------------
// C[m][n] = bias(n) + sum_k A(m)[k] * B(n)[k]
// REQUIRES: M%128==0, N%128==0, K%32==0, msplit/nsplit multiples of 128.
__global__ void __launch_bounds__(256)
gemm_tf32(int M, int N, int K,
          const float* __restrict__ A0, const float* __restrict__ A1, int msplit, int lda,
          const float* __restrict__ B0, const float* __restrict__ B1, int nsplit, int ldb,
          const float* __restrict__ bias0, const float* __restrict__ bias1,
          float* __restrict__ C, int ldc)
{
    constexpr int BM = 128, BN = 128, BK = 32, PAD = 4;
    __shared__ uint32_t As[BM][BK + PAD];
    __shared__ uint32_t Bs[BN][BK + PAD];

    const int tid  = threadIdx.x;
    const int lane = tid & 31;
    const int warp = tid >> 5;
    const int wm0 = (warp & 1) * 64;
    const int wn0 = (warp >> 1) * 32;
    const int bm = blockIdx.y * BM;
    const int bn = blockIdx.x * BN;
    const int g  = lane >> 2;
    const int tg = lane & 3;

    float acc[4][4][4];
    #pragma unroll
    for (int i = 0; i < 4; i++)
        #pragma unroll
        for (int j = 0; j < 4; j++)
            #pragma unroll
            for (int r = 0; r < 4; r++) acc[i][j][r] = 0.f;

    for (int k0 = 0; k0 < K; k0 += BK) {
        #pragma unroll
        for (int p = tid; p < BM * (BK/4); p += 256) {
            int row = p >> 3, cv = (p & 7) * 4;
            int m = bm + row;
            const float* a = (m < msplit) ? (A0 + (size_t)m * lda)
                                          : (A1 + (size_t)(m - msplit) * lda);
            float4 v = *(const float4*)(a + k0 + cv);
            As[row][cv+0] = f2tf32(v.x); As[row][cv+1] = f2tf32(v.y);
            As[row][cv+2] = f2tf32(v.z); As[row][cv+3] = f2tf32(v.w);
        }
        #pragma unroll
        for (int p = tid; p < BN * (BK/4); p += 256) {
            int row = p >> 3, cv = (p & 7) * 4;
            int n = bn + row;
            const float* b = (n < nsplit) ? (B0 + (size_t)n * ldb)
                                          : (B1 + (size_t)(n - nsplit) * ldb);
            float4 v = *(const float4*)(b + k0 + cv);
            Bs[row][cv+0] = f2tf32(v.x); Bs[row][cv+1] = f2tf32(v.y);
            Bs[row][cv+2] = f2tf32(v.z); Bs[row][cv+3] = f2tf32(v.w);
        }
        __syncthreads();

        #pragma unroll
        for (int kk = 0; kk < 4; kk++) {
            const int kb = kk * 8;
            uint32_t af[4][4];
            #pragma unroll
            for (int i = 0; i < 4; i++) {
                int r0 = wm0 + i * 16 + g;
                af[i][0] = As[r0    ][kb + tg    ];
                af[i][1] = As[r0 + 8][kb + tg    ];
                af[i][2] = As[r0    ][kb + tg + 4];
                af[i][3] = As[r0 + 8][kb + tg + 4];
            }
            uint32_t bf[4][2];
            #pragma unroll
            for (int j = 0; j < 4; j++) {
                int n0 = wn0 + j * 8 + g;
                bf[j][0] = Bs[n0][kb + tg    ];
                bf[j][1] = Bs[n0][kb + tg + 4];
            }
            #pragma unroll
            for (int i = 0; i < 4; i++)
                #pragma unroll
                for (int j = 0; j < 4; j++)
                    mma_tf32(acc[i][j], af[i][0], af[i][1], af[i][2], af[i][3],
                             bf[j][0], bf[j][1]);
        }
        __syncthreads();
    }

    #pragma unroll
    for (int i = 0; i < 4; i++) {
        int row = bm + wm0 + i * 16 + g;
        #pragma unroll
        for (int j = 0; j < 4; j++) {
            int col = bn + wn0 + j * 8 + 2 * tg;
            float bv0 = 0.f, bv1 = 0.f;
            if (bias0) {
                const float* bp = (col < nsplit) ? (bias0 + col) : (bias1 + col - nsplit);
                bv0 = bp[0]; bv1 = bp[1];
            }
            float2 v0 = make_float2(acc[i][j][0] + bv0, acc[i][j][1] + bv1);
            float2 v1 = make_float2(acc[i][j][2] + bv0, acc[i][j][3] + bv1);
            *(float2*)(C + (size_t)row * ldc + col)       = v0;
            *(float2*)(C + (size_t)(row + 8) * ldc + col) = v1;
        }
    }
}

// ---------------- pack W_hh into tf32 hi/lo (once; reused 48x) ----------------
__global__ void pack_whh(const float* __restrict__ Wf, const float* __restrict__ Wb,
                         uint32_t* __restrict__ Whi, uint32_t* __restrict__ Wlo)
{
    int idx = blockIdx.x * blockDim.x + threadIdx.x;
    if (idx >= 2 * G3H * H_GRU) return;
    float v = (idx < G3H * H_GRU) ? Wf[idx] : Wb[idx - G3H * H_GRU];
    uint32_t hi = f2tf32(v);
    Whi[idx] = hi;
    Wlo[idx] = f2tf32(v - __uint_as_float(hi));
}

// ---------------- GRU hh GEMM: 3xTF32, split-K over 2 slices ----------------
// partial(ks,dir)[m][n] = [ks==0]*bias + sum_{k in slice} h[m][k]*W[n][k]
// grid (G3H/64, NSEQ/64, 2*KSPLIT): z = dir + 2*ks. 256 threads; K-slice = 256.
__global__ void __launch_bounds__(256)
gemm_hh_tf32(const float* __restrict__ h,
             const uint32_t* __restrict__ Whi, const uint32_t* __restrict__ Wlo,
             const float* __restrict__ bf_, const float* __restrict__ bb_,
             float* __restrict__ hg)
{
    constexpr int BK = 32, PAD = 4;
    constexpr int KSL = H_GRU / KSPLIT;      // 256
    __shared__ uint32_t As_hi[64][BK + PAD];
    __shared__ uint32_t As_lo[64][BK + PAD];
    __shared__ uint32_t Bs_hi[64][BK + PAD];
    __shared__ uint32_t Bs_lo[64][BK + PAD];

    const int tid  = threadIdx.x;
    const int lane = tid & 31;
    const int warp = tid >> 5;
    const int wm0 = (warp & 1) * 32;
    const int wn0 = (warp >> 1) * 16;
    const int g  = lane >> 2;
    const int tg = lane & 3;

    const int dir = blockIdx.z & 1;
    const int ks  = blockIdx.z >> 1;
    const int kbase = ks * KSL;
    const int m0 = blockIdx.y * 64;
    const int n0t = blockIdx.x * 64;
    const float* A = h + (size_t)dir * NSEQ * H_GRU;
    const uint32_t* Bh = Whi + (size_t)dir * G3H * H_GRU;
    const uint32_t* Bl = Wlo + (size_t)dir * G3H * H_GRU;
    const float* bias = dir ? bb_ : bf_;
    float* C = hg + ((size_t)ks * 2 + dir) * NSEQ * G3H;

    float acc[2][2][4];
    #pragma unroll
    for (int i = 0; i < 2; i++)
        #pragma unroll
        for (int j = 0; j < 2; j++)
            #pragma unroll
            for (int r = 0; r < 4; r++) acc[i][j][r] = 0.f;

    float4 pa[2];
    uint4  pbh[2], pbl[2];
    #pragma unroll
    for (int i = 0; i < 2; i++) {
        int p = tid + i * 256, row = p >> 3, kc = (p & 7) * 4;
        pa[i]  = *(const float4*)(A  + (size_t)(m0 + row) * H_GRU + kbase + kc);
        pbh[i] = *(const uint4*)(Bh + (size_t)(n0t + row) * H_GRU + kbase + kc);
        pbl[i] = *(const uint4*)(Bl + (size_t)(n0t + row) * H_GRU + kbase + kc);
    }

    for (int k0 = 0; k0 < KSL; k0 += BK) {
        #pragma unroll
        for (int i = 0; i < 2; i++) {
            int p = tid + i * 256, row = p >> 3, kc = (p & 7) * 4;
            float av[4] = {pa[i].x, pa[i].y, pa[i].z, pa[i].w};
            #pragma unroll
            for (int e = 0; e < 4; e++) {
                uint32_t ah = f2tf32(av[e]);
                As_hi[row][kc + e] = ah;
                As_lo[row][kc + e] = f2tf32(av[e] - __uint_as_float(ah));
            }
            Bs_hi[row][kc+0] = pbh[i].x; Bs_hi[row][kc+1] = pbh[i].y;
            Bs_hi[row][kc+2] = pbh[i].z; Bs_hi[row][kc+3] = pbh[i].w;
            Bs_lo[row][kc+0] = pbl[i].x; Bs_lo[row][kc+1] = pbl[i].y;
            Bs_lo[row][kc+2] = pbl[i].z; Bs_lo[row][kc+3] = pbl[i].w;
        }
        __syncthreads();
        if (k0 + BK < KSL) {
            #pragma unroll
            for (int i = 0; i < 2; i++) {
                int p = tid + i * 256, row = p >> 3, kc = (p & 7) * 4;
                pa[i]  = *(const float4*)(A  + (size_t)(m0 + row) * H_GRU + kbase + k0 + BK + kc);
                pbh[i] = *(const uint4*)(Bh + (size_t)(n0t + row) * H_GRU + kbase + k0 + BK + kc);
                pbl[i] = *(const uint4*)(Bl + (size_t)(n0t + row) * H_GRU + kbase + k0 + BK + kc);
            }
        }
        #pragma unroll
        for (int kk = 0; kk < 4; kk++) {
            const int kb = kk * 8;
            uint32_t ah[2][4], al[2][4], bh[2][2], bl[2][2];
            #pragma unroll
            for (int i = 0; i < 2; i++) {
                int r0 = wm0 + i * 16 + g;
                ah[i][0] = As_hi[r0    ][kb + tg    ];
                ah[i][1] = As_hi[r0 + 8][kb + tg    ];
                ah[i][2] = As_hi[r0    ][kb + tg + 4];
                ah[i][3] = As_hi[r0 + 8][kb + tg + 4];
                al[i][0] = As_lo[r0    ][kb + tg    ];
                al[i][1] = As_lo[r0 + 8][kb + tg    ];
                al[i][2] = As_lo[r0    ][kb + tg + 4];
                al[i][3] = As_lo[r0 + 8][kb + tg + 4];
            }
            #pragma unroll
            for (int j = 0; j < 2; j++) {
                int nn = wn0 + j * 8 + g;
                bh[j][0] = Bs_hi[nn][kb + tg    ];
                bh[j][1] = Bs_hi[nn][kb + tg + 4];
                bl[j][0] = Bs_lo[nn][kb + tg    ];
                bl[j][1] = Bs_lo[nn][kb + tg + 4];
            }
            #pragma unroll
            for (int i = 0; i < 2; i++)
                #pragma unroll
                for (int j = 0; j < 2; j++) {
                    mma_tf32(acc[i][j], al[i][0], al[i][1], al[i][2], al[i][3],
                             bh[j][0], bh[j][1]);
                    mma_tf32(acc[i][j], ah[i][0], ah[i][1], ah[i][2], ah[i][3],
                             bl[j][0], bl[j][1]);
                    mma_tf32(acc[i][j], ah[i][0], ah[i][1], ah[i][2], ah[i][3],
                             bh[j][0], bh[j][1]);
                }
        }
        __syncthreads();
    }

    #pragma unroll
    for (int i = 0; i < 2; i++) {
        int row = m0 + wm0 + i * 16 + g;
        #pragma unroll
        for (int j = 0; j < 2; j++) {
            int col = n0t + wn0 + j * 8 + 2 * tg;
            float bv0 = 0.f, bv1 = 0.f;
            if (ks == 0) { bv0 = bias[col]; bv1 = bias[col + 1]; }
            float2 v0 = make_float2(acc[i][j][0] + bv0, acc[i][j][1] + bv1);
            float2 v1 = make_float2(acc[i][j][2] + bv0, acc[i][j][3] + bv1);
            *(float2*)(C + (size_t)row * G3H + col)       = v0;
            *(float2*)(C + (size_t)(row + 8) * G3H + col) = v1;
        }
    }
}

// ---------------- fp32 SIMT NT GEMM (small GEMMs) ----------------
template<int BM, int BN, int BK, int TM, int TN>
__global__ void __launch_bounds__((BM/TM)*(BN/TN))
gemm_nt(int M, int N, int K,
        const float* __restrict__ A0, const float* __restrict__ A1, int msplit, int lda,
        const float* __restrict__ B, int ldb,
        const float* __restrict__ bias,
        float* __restrict__ C, int ldc)
{
    constexpr int THREADS = (BM/TM)*(BN/TN);
    constexpr int KV = BK/4;
    __shared__ float Ast[BK][BM];
    __shared__ float Bst[BK][BN];
    const int tid = threadIdx.x;
    const int bm = blockIdx.y * BM;
    const int bn = blockIdx.x * BN;
    const int tx = tid % (BN/TN);
    const int ty = tid / (BN/TN);

    float acc[TM][TN];
    #pragma unroll
    for (int i = 0; i < TM; i++)
        #pragma unroll
        for (int j = 0; j < TN; j++) acc[i][j] = 0.f;

    for (int k0 = 0; k0 < K; k0 += BK) {
        #pragma unroll
        for (int p = tid; p < BM*KV; p += THREADS) {
            int row = p / KV;
            int kc  = (p % KV) * 4;
            int m = bm + row;
            float4 v = make_float4(0.f, 0.f, 0.f, 0.f);
            if (m < M) {
                const float* a = (m < msplit) ? (A0 + (size_t)m * lda)
                                              : (A1 + (size_t)(m - msplit) * lda);
                v = *(const float4*)(a + k0 + kc);
            }
            Ast[kc+0][row] = v.x; Ast[kc+1][row] = v.y;
            Ast[kc+2][row] = v.z; Ast[kc+3][row] = v.w;
        }
        #pragma unroll
        for (int p = tid; p < BN*KV; p += THREADS) {
            int row = p / KV;
            int kc  = (p % KV) * 4;
            int n = bn + row;
            float4 v = make_float4(0.f, 0.f, 0.f, 0.f);
            if (n < N) v = *(const float4*)(B + (size_t)n * ldb + k0 + kc);
            Bst[kc+0][row] = v.x; Bst[kc+1][row] = v.y;
            Bst[kc+2][row] = v.z; Bst[kc+3][row] = v.w;
        }
        __syncthreads();
        #pragma unroll
        for (int kk = 0; kk < BK; kk++) {
            float ra[TM], rb[TN];
            #pragma unroll
            for (int i = 0; i < TM; i += 4)
                *(float4*)&ra[i] = *(const float4*)&Ast[kk][ty*TM + i];
            #pragma unroll
            for (int j = 0; j < TN; j += 4)
                *(float4*)&rb[j] = *(const float4*)&Bst[kk][tx*TN + j];
            #pragma unroll
            for (int i = 0; i < TM; i++)
                #pragma unroll
                for (int j = 0; j < TN; j++)
                    acc[i][j] = fmaf(ra[i], rb[j], acc[i][j]);
        }
        __syncthreads();
    }
    #pragma unroll
    for (int i = 0; i < TM; i++) {
        int m = bm + ty*TM + i;
        if (m >= M) continue;
        #pragma unroll
        for (int j = 0; j < TN; j += 4) {
            int n = bn + tx*TN + j;
            float4 v;
            v.x = acc[i][j+0]; v.y = acc[i][j+1];
            v.z = acc[i][j+2]; v.w = acc[i][j+3];
            if (bias) { v.x += bias[n]; v.y += bias[n+1]; v.z += bias[n+2]; v.w += bias[n+3]; }
            *(float4*)(C + (size_t)m * ldc + n) = v;
        }
    }
}

// ---------------- misc kernels ----------------
__global__ void zero_kernel(float* p, int n) {
    int i = blockIdx.x * blockDim.x + threadIdx.x;
    if (i < n) p[i] = 0.f;
}

// one GRU timestep; sums the KSPLIT hg partial slices
__global__ void gru_step(const float* __restrict__ xg,
                         const float* __restrict__ hg_all,
                         float* __restrict__ h_all,
                         const float* __restrict__ vmask, const float* __restrict__ smask,
                         float* __restrict__ gru, int s)
{
    int idx = blockIdx.x * blockDim.x + threadIdx.x;
    if (idx >= 2 * NSEQ * (H_GRU / 4)) return;
    const int JW = H_GRU / 4;
    int dir = idx / (NSEQ * JW);
    int r = idx - dir * NSEQ * JW;
    int n = r / JW;
    int j4 = (r - n * JW) * 4;
    int t = dir ? (T_FRAMES - 1 - s) : s;

    size_t xo = ((size_t)n * T_FRAMES + t) * (2 * G3H) + (size_t)dir * G3H;
    float4 xr = *(const float4*)(xg + xo + j4);
    float4 xz = *(const float4*)(xg + xo + H_GRU + j4);
    float4 xn = *(const float4*)(xg + xo + 2*H_GRU + j4);

    const float* hg0 = hg_all + (size_t)dir * NSEQ * G3H + (size_t)n * G3H;
    const float* hg1 = hg0 + (size_t)2 * NSEQ * G3H;     // ks=1 slice
    float4 hr0 = *(const float4*)(hg0 + j4);
    float4 hz0 = *(const float4*)(hg0 + H_GRU + j4);
    float4 hn0 = *(const float4*)(hg0 + 2*H_GRU + j4);
    float4 hr1 = *(const float4*)(hg1 + j4);
    float4 hz1 = *(const float4*)(hg1 + H_GRU + j4);
    float4 hn1 = *(const float4*)(hg1 + 2*H_GRU + j4);

    float* hp = h_all + (size_t)dir * NSEQ * H_GRU + (size_t)n * H_GRU + j4;
    float4 hold = *(float4*)hp;

    float mval = (n < NB) ? vmask[n * T_FRAMES + t]
                          : smask[(n - NB) * T_FRAMES + t];

    float xrv[4] = {xr.x, xr.y, xr.z, xr.w};
    float xzv[4] = {xz.x, xz.y, xz.z, xz.w};
    float xnv[4] = {xn.x, xn.y, xn.z, xn.w};
    float hrv[4] = {hr0.x + hr1.x, hr0.y + hr1.y, hr0.z + hr1.z, hr0.w + hr1.w};
    float hzv[4] = {hz0.x + hz1.x, hz0.y + hz1.y, hz0.z + hz1.z, hz0.w + hz1.w};
    float hnv[4] = {hn0.x + hn1.x, hn0.y + hn1.y, hn0.z + hn1.z, hn0.w + hn1.w};
    float hov[4] = {hold.x, hold.y, hold.z, hold.w};
    float outv[4], gw[4];
    #pragma unroll
    for (int e = 0; e < 4; e++) {
        float rg = 1.f / (1.f + __expf(-(xrv[e] + hrv[e])));
        float zg = 1.f / (1.f + __expf(-(xzv[e] + hzv[e])));
        float ng = __tanhf(xnv[e] + rg * hnv[e]);
        float hv = (1.f - zg) * ng + zg * hov[e];
        outv[e] = hv;
        gw[e] = hv * mval;
    }
    *(float4*)hp = make_float4(outv[0], outv[1], outv[2], outv[3]);
    *(float4*)(gru + ((size_t)n * T_FRAMES + t) * C2H + dir * H_GRU + j4) =
        make_float4(gw[0], gw[1], gw[2], gw[3]);
}

__global__ void pool_origin(const float* __restrict__ gru,
                            const int* __restrict__ len, const int* __restrict__ slen,
                            const float* __restrict__ vorig, const float* __restrict__ sorig,
                            float* __restrict__ feat)
{
    int idx = blockIdx.x * blockDim.x + threadIdx.x;
    if (idx >= NSEQ * (C2H + D_IN)) return;
    int n = idx / (C2H + D_IN);
    int c = idx - n * (C2H + D_IN);
    if (c < C2H) {
        const float* g = gru + (size_t)n * T_FRAMES * C2H + c;
        float s = 0.f;
        #pragma unroll
        for (int t = 0; t < T_FRAMES; t++) s += g[(size_t)t * C2H];
        int L = (n < NB) ? len[n] : slen[n - NB];
        feat[(size_t)n * FEATD + c] = s / (float)L;
    } else {
        int cc = c - C2H;
        float v = (n < NB) ? vorig[(size_t)n * D_IN + cc]
                           : sorig[(size_t)(n - NB) * D_IN + cc];
        feat[(size_t)n * FEATD + (C2H + 4*512) + cc] = v;
    }
}

__global__ void pack_conv(const float* __restrict__ w2, const float* __restrict__ w3,
                          const float* __restrict__ w4, const float* __restrict__ w5,
                          float* __restrict__ Bc)
{
    int idx = blockIdx.x * blockDim.x + threadIdx.x;
    if (idx >= NCONV * C2H) return;
    int col = idx / C2H;
    int c = idx - col * C2H;
    int w, k, i; const float* src;
    if (col < 1024)      { w = 2; src = w2; int r = col;        k = r / 2; i = r - k*2; }
    else if (col < 2560) { w = 3; src = w3; int r = col - 1024; k = r / 3; i = r - k*3; }
    else if (col < 4608) { w = 4; src = w4; int r = col - 2560; k = r / 4; i = r - k*4; }
    else                 { w = 5; src = w5; int r = col - 4608; k = r / 5; i = r - k*5; }
    Bc[(size_t)col * C2H + c] = src[((size_t)k * C2H + c) * w + i];
}

__global__ void conv_reduce(const float* __restrict__ P,
                            const float* __restrict__ cb2, const float* __restrict__ cb3,
                            const float* __restrict__ cb4, const float* __restrict__ cb5,
                            float* __restrict__ feat)
{
    int idx = blockIdx.x * blockDim.x + threadIdx.x;
    if (idx >= NSEQ * 2048) return;
    int n = idx / 2048;
    int c = idx - n * 2048;
    int widx = c >> 9;
    int k = c & 511;
    int w = widx + 2;
    int base = (widx == 0) ? 0 : (widx == 1) ? 1024 : (widx == 2) ? 2560 : 4608;
    const float* cb = (widx == 0) ? cb2 : (widx == 1) ? cb3 : (widx == 2) ? cb4 : cb5;
    float bb = cb[k];
    const float* Pn = P + (size_t)n * T_FRAMES * NCONV + base + k * w;
    float best = 0.f;
    for (int tau = 0; tau < T_FRAMES + w - 1; tau++) {
        float y = bb;
        for (int i = 0; i < w; i++) {
            int t = tau + i - (w - 1);
            if (t >= 0 && t < T_FRAMES) y += Pn[(size_t)t * NCONV + i];
        }
        best = fmaxf(best, y);
    }
    feat[(size_t)n * FEATD + C2H + c] = best;
}

__global__ void attn_out(const float* __restrict__ feat, const float* __restrict__ q,
                         const float* __restrict__ kf, float* __restrict__ out)
{
    int b = blockIdx.x;
    int tid = threadIdx.x;
    __shared__ float logits[NS];
    __shared__ float wgt[NS];
    if (tid < 32 * NS) {
        int s = tid >> 5, lane = tid & 31;
        const float* kk = kf + (size_t)(b * NS + s) * 512;
        const float* qq = q + (size_t)b * 512;
        float sum = 0.f;
        for (int h = lane; h < 512; h += 32) sum += kk[h] * qq[h];
        #pragma unroll
        for (int o = 16; o; o >>= 1) sum += __shfl_down_sync(0xffffffffu, sum, o);
        if (lane == 0) logits[s] = sum;
    }
    __syncthreads();
    if (tid == 0) {
        float mx = fmaxf(fmaxf(logits[0], logits[1]), fmaxf(logits[2], logits[3]));
        float e0 = expf(logits[0]-mx), e1 = expf(logits[1]-mx);
        float e2 = expf(logits[2]-mx), e3 = expf(logits[3]-mx);
        float se = e0 + e1 + e2 + e3;
        wgt[0] = e0/se; wgt[1] = e1/se; wgt[2] = e2/se; wgt[3] = e3/se;
    }
    __syncthreads();
    float w0 = wgt[0], w1 = wgt[1], w2 = wgt[2], w3 = wgt[3];
    const float* f0 = feat + (size_t)b * FEATD;
    const float* s0 = feat + (size_t)(NB + b * NS) * FEATD;
    for (int f = tid; f < FEATD; f += blockDim.x) {
        out[(size_t)b * FEATD + f] = f0[f]
            + w0 * s0[f] + w1 * s0[FEATD + f]
            + w2 * s0[2*(size_t)FEATD + f] + w3 * s0[3*(size_t)FEATD + f];
    }
}

// ---------------- launch ----------------
extern "C" void kernel_launch(void* const* d_in, const int* in_sizes, int n_in,
                              void* d_out, int out_size)
{
    const float* videos   = (const float*)d_in[0];
    const float* vorigin  = (const float*)d_in[1];
    const int*   lengths  = (const int*)  d_in[2];
    const float* vmask    = (const float*)d_in[3];
    const float* svideos  = (const float*)d_in[4];
    const float* sorigin  = (const float*)d_in[5];
    const int*   slengths = (const int*)  d_in[6];
    const float* smask    = (const float*)d_in[7];
    const float* W_ih_f = (const float*)d_in[10];
    const float* W_hh_f = (const float*)d_in[11];
    const float* b_ih_f = (const float*)d_in[12];
    const float* b_hh_f = (const float*)d_in[13];
    const float* W_ih_b = (const float*)d_in[14];
    const float* W_hh_b = (const float*)d_in[15];
    const float* b_ih_b = (const float*)d_in[16];
    const float* b_hh_b = (const float*)d_in[17];
    const float* cw2 = (const float*)d_in[18]; const float* cb2 = (const float*)d_in[19];
    const float* cw3 = (const float*)d_in[20]; const float* cb3 = (const float*)d_in[21];
    const float* cw4 = (const float*)d_in[22]; const float* cb4 = (const float*)d_in[23];
    const float* cw5 = (const float*)d_in[24]; const float* cb5 = (const float*)d_in[25];
    const float* Wk = (const float*)d_in[26]; const float* bk = (const float*)d_in[27];
    const float* Wq = (const float*)d_in[28]; const float* bq = (const float*)d_in[29];
    float* out = (float*)d_out;

    float *p_xg, *p_h, *p_hg, *p_gru, *p_Bc, *p_P, *p_feat, *p_q, *p_k;
    uint32_t *p_Whi, *p_Wlo;
    cudaGetSymbolAddress((void**)&p_xg,   g_xg);
    cudaGetSymbolAddress((void**)&p_h,    g_h);
    cudaGetSymbolAddress((void**)&p_hg,   g_hg);
    cudaGetSymbolAddress((void**)&p_gru,  g_gru);
    cudaGetSymbolAddress((void**)&p_Bc,   g_Bc);
    cudaGetSymbolAddress((void**)&p_P,    g_P);
    cudaGetSymbolAddress((void**)&p_feat, g_feat);
    cudaGetSymbolAddress((void**)&p_q,    g_q);
    cudaGetSymbolAddress((void**)&p_k,    g_k);
    cudaGetSymbolAddress((void**)&p_Whi,  g_Whi);
    cudaGetSymbolAddress((void**)&p_Wlo,  g_Wlo);

    zero_kernel<<<(2*NSEQ*H_GRU + 255)/256, 256>>>(p_h, 2*NSEQ*H_GRU);
    pack_whh<<<(2*G3H*H_GRU + 255)/256, 256>>>(W_hh_f, W_hh_b, p_Whi, p_Wlo);

    // fused fwd+bwd input projection: [15360 x 2048] x [3072 x 2048]^T (tf32)
    gemm_tf32<<<dim3(2*G3H/128, M_ALL/128), 256>>>(M_ALL, 2*G3H, D_IN,
        videos, svideos, MAIN_ROWS, D_IN,
        W_ih_f, W_ih_b, G3H, D_IN,
        b_ih_f, b_ih_b, p_xg, 2*G3H);

    pack_conv<<<(NCONV*C2H + 255)/256, 256>>>(cw2, cw3, cw4, cw5, p_Bc);

    // GRU recurrence: split-K hh GEMM (480 CTAs) + gate kernel summing partials
    for (int s = 0; s < T_FRAMES; s++) {
        gemm_hh_tf32<<<dim3(G3H/64, NSEQ/64, 2*KSPLIT), 256>>>(
            p_h, p_Whi, p_Wlo, b_hh_f, b_hh_b, p_hg);
        gru_step<<<(2*NSEQ*(H_GRU/4) + 255)/256, 256>>>(
            p_xg, p_hg, p_h, vmask, smask, p_gru, s);
    }

    pool_origin<<<(NSEQ*(C2H + D_IN) + 255)/256, 256>>>(
        p_gru, lengths, slengths, vorigin, sorigin, p_feat);

    // conv-as-GEMM: [15360 x 1024] x [7168 x 1024]^T (tf32)
    gemm_tf32<<<dim3(NCONV/128, M_ALL/128), 256>>>(M_ALL, NCONV, C2H,
        p_gru, p_gru, M_ALL, C2H,
        p_Bc, p_Bc, NCONV, C2H,
        nullptr, nullptr, p_P, NCONV);
    conv_reduce<<<(NSEQ*2048 + 255)/256, 256>>>(p_P, cb2, cb3, cb4, cb5, p_feat);

    // query / key projections (fp32)
    gemm_nt<64,64,16,4,4><<<dim3(512/64, 1), 256>>>(NB, 512, FEATD,
        p_feat, p_feat, NB, FEATD, Wq, FEATD, bq, p_q, 512);
    gemm_nt<64,64,16,4,4><<<dim3(512/64, 4), 256>>>(NB*NS, 512, FEATD,
        p_feat + (size_t)NB*FEATD, p_feat + (size_t)NB*FEATD, NB*NS, FEATD,
        Wk, FEATD, bk, p_k, 512);

    attn_out<<<NB, 256>>>(p_feat, p_q, p_k, out);
}

// round 9
// speedup vs baseline: 1.1916x; 1.0184x over previous
#include <cuda_runtime.h>
#include <cstdint>
#include <cstddef>

// ---------------- problem constants ----------------
#define T_FRAMES 48
#define D_IN     2048
#define H_GRU    512
#define G3H      1536      // 3*H
#define C2H      1024      // 2*H
#define NSEQ     320       // 64 main + 256 support
#define MAIN_ROWS 3072     // 64*48
#define M_ALL    15360     // 320*48
#define NCONV    7168      // 512*(2+3+4+5)
#define FEATD    5120
#define NB       64
#define NS       4
#define KSPLIT   4         // split-K factor for hh GEMM (K=512 -> 4 x 128)

// ---------------- device scratch ----------------
__device__ float    g_xg [(size_t)M_ALL * 2 * G3H];
__device__ float    g_h  [2 * NSEQ * H_GRU];
__device__ float    g_hg [KSPLIT * 2 * NSEQ * G3H];       // [ks][dir][n][g] partials
__device__ float    g_gru[(size_t)NSEQ * T_FRAMES * C2H];
__device__ float    g_Bc [(size_t)NCONV * C2H];
__device__ float    g_P  [(size_t)M_ALL * NCONV];
__device__ float    g_feat[(size_t)NSEQ * FEATD];
__device__ float    g_q  [NB * 512];
__device__ float    g_k  [NB * NS * 512];
__device__ uint32_t g_Whi[2 * G3H * H_GRU];   // tf32 hi of W_hh (both dirs), packed once
__device__ uint32_t g_Wlo[2 * G3H * H_GRU];   // tf32 lo residual

// ---------------- tf32 helpers ----------------
__device__ __forceinline__ uint32_t f2tf32(float f) {
    uint32_t u;
    asm("cvt.rna.tf32.f32 %0, %1;" : "=r"(u) : "f"(f));
    return u;
}
__device__ __forceinline__ void mma_tf32(float c[4], uint32_t a0, uint32_t a1,
                                         uint32_t a2, uint32_t a3,
                                         uint32_t b0, uint32_t b1) {
    asm volatile(
        "mma.sync.aligned.m16n8k8.row.col.f32.tf32.tf32.f32 "
        "{%0,%1,%2,%3}, {%4,%5,%6,%7}, {%8,%9}, {%0,%1,%2,%3};"
        : "+f"(c[0]), "+f"(c[1]), "+f"(c[2]), "+f"(c[3])
        : "r"(a0), "r"(a1), "r"(a2), "r"(a3), "r"(b0), "r"(b1));
}

// ---------------- tf32 tensor-core NT GEMM (round-2/6 proven, single-buffer) ----------------
// C[m][n] = bias(n) + sum_k A(m)[k] * B(n)[k]
// REQUIRES: M%128==0, N%128==0, K%32==0, msplit/nsplit multiples of 128.
__global__ void __launch_bounds__(256)
gemm_tf32(int M, int N, int K,
          const float* __restrict__ A0, const float* __restrict__ A1, int msplit, int lda,
          const float* __restrict__ B0, const float* __restrict__ B1, int nsplit, int ldb,
          const float* __restrict__ bias0, const float* __restrict__ bias1,
          float* __restrict__ C, int ldc)
{
    constexpr int BM = 128, BN = 128, BK = 32, PAD = 4;
    __shared__ uint32_t As[BM][BK + PAD];
    __shared__ uint32_t Bs[BN][BK + PAD];

    const int tid  = threadIdx.x;
    const int lane = tid & 31;
    const int warp = tid >> 5;
    const int wm0 = (warp & 1) * 64;
    const int wn0 = (warp >> 1) * 32;
    const int bm = blockIdx.y * BM;
    const int bn = blockIdx.x * BN;
    const int g  = lane >> 2;
    const int tg = lane & 3;

    float acc[4][4][4];
    #pragma unroll
    for (int i = 0; i < 4; i++)
        #pragma unroll
        for (int j = 0; j < 4; j++)
            #pragma unroll
            for (int r = 0; r < 4; r++) acc[i][j][r] = 0.f;

    for (int k0 = 0; k0 < K; k0 += BK) {
        #pragma unroll
        for (int p = tid; p < BM * (BK/4); p += 256) {
            int row = p >> 3, cv = (p & 7) * 4;
            int m = bm + row;
            const float* a = (m < msplit) ? (A0 + (size_t)m * lda)
                                          : (A1 + (size_t)(m - msplit) * lda);
            float4 v = *(const float4*)(a + k0 + cv);
            As[row][cv+0] = f2tf32(v.x); As[row][cv+1] = f2tf32(v.y);
            As[row][cv+2] = f2tf32(v.z); As[row][cv+3] = f2tf32(v.w);
        }
        #pragma unroll
        for (int p = tid; p < BN * (BK/4); p += 256) {
            int row = p >> 3, cv = (p & 7) * 4;
            int n = bn + row;
            const float* b = (n < nsplit) ? (B0 + (size_t)n * ldb)
                                          : (B1 + (size_t)(n - nsplit) * ldb);
            float4 v = *(const float4*)(b + k0 + cv);
            Bs[row][cv+0] = f2tf32(v.x); Bs[row][cv+1] = f2tf32(v.y);
            Bs[row][cv+2] = f2tf32(v.z); Bs[row][cv+3] = f2tf32(v.w);
        }
        __syncthreads();

        #pragma unroll
        for (int kk = 0; kk < 4; kk++) {
            const int kb = kk * 8;
            uint32_t af[4][4];
            #pragma unroll
            for (int i = 0; i < 4; i++) {
                int r0 = wm0 + i * 16 + g;
                af[i][0] = As[r0    ][kb + tg    ];
                af[i][1] = As[r0 + 8][kb + tg    ];
                af[i][2] = As[r0    ][kb + tg + 4];
                af[i][3] = As[r0 + 8][kb + tg + 4];
            }
            uint32_t bf[4][2];
            #pragma unroll
            for (int j = 0; j < 4; j++) {
                int n0 = wn0 + j * 8 + g;
                bf[j][0] = Bs[n0][kb + tg    ];
                bf[j][1] = Bs[n0][kb + tg + 4];
            }
            #pragma unroll
            for (int i = 0; i < 4; i++)
                #pragma unroll
                for (int j = 0; j < 4; j++)
                    mma_tf32(acc[i][j], af[i][0], af[i][1], af[i][2], af[i][3],
                             bf[j][0], bf[j][1]);
        }
        __syncthreads();
    }

    #pragma unroll
    for (int i = 0; i < 4; i++) {
        int row = bm + wm0 + i * 16 + g;
        #pragma unroll
        for (int j = 0; j < 4; j++) {
            int col = bn + wn0 + j * 8 + 2 * tg;
            float bv0 = 0.f, bv1 = 0.f;
            if (bias0) {
                const float* bp = (col < nsplit) ? (bias0 + col) : (bias1 + col - nsplit);
                bv0 = bp[0]; bv1 = bp[1];
            }
            float2 v0 = make_float2(acc[i][j][0] + bv0, acc[i][j][1] + bv1);
            float2 v1 = make_float2(acc[i][j][2] + bv0, acc[i][j][3] + bv1);
            *(float2*)(C + (size_t)row * ldc + col)       = v0;
            *(float2*)(C + (size_t)(row + 8) * ldc + col) = v1;
        }
    }
}

// ---------------- pack W_hh into tf32 hi/lo (once; reused 48x) ----------------
__global__ void pack_whh(const float* __restrict__ Wf, const float* __restrict__ Wb,
                         uint32_t* __restrict__ Whi, uint32_t* __restrict__ Wlo)
{
    int idx = blockIdx.x * blockDim.x + threadIdx.x;
    if (idx >= 2 * G3H * H_GRU) return;
    float v = (idx < G3H * H_GRU) ? Wf[idx] : Wb[idx - G3H * H_GRU];
    uint32_t hi = f2tf32(v);
    Whi[idx] = hi;
    Wlo[idx] = f2tf32(v - __uint_as_float(hi));
}

// ---------------- GRU hh GEMM: 3xTF32, split-K over 4 slices ----------------
// partial(ks,dir)[m][n] = [ks==0]*bias + sum_{k in slice} h[m][k]*W[n][k]
// grid (G3H/64, NSEQ/64, 2*KSPLIT): z = dir + 2*ks. 256 threads; K-slice = 128.
__global__ void __launch_bounds__(256)
gemm_hh_tf32(const float* __restrict__ h,
             const uint32_t* __restrict__ Whi, const uint32_t* __restrict__ Wlo,
             const float* __restrict__ bf_, const float* __restrict__ bb_,
             float* __restrict__ hg)
{
    constexpr int BK = 32, PAD = 4;
    constexpr int KSL = H_GRU / KSPLIT;      // 128
    __shared__ uint32_t As_hi[64][BK + PAD];
    __shared__ uint32_t As_lo[64][BK + PAD];
    __shared__ uint32_t Bs_hi[64][BK + PAD];
    __shared__ uint32_t Bs_lo[64][BK + PAD];

    const int tid  = threadIdx.x;
    const int lane = tid & 31;
    const int warp = tid >> 5;
    const int wm0 = (warp & 1) * 32;
    const int wn0 = (warp >> 1) * 16;
    const int g  = lane >> 2;
    const int tg = lane & 3;

    const int dir = blockIdx.z & 1;
    const int ks  = blockIdx.z >> 1;
    const int kbase = ks * KSL;
    const int m0 = blockIdx.y * 64;
    const int n0t = blockIdx.x * 64;
    const float* A = h + (size_t)dir * NSEQ * H_GRU;
    const uint32_t* Bh = Whi + (size_t)dir * G3H * H_GRU;
    const uint32_t* Bl = Wlo + (size_t)dir * G3H * H_GRU;
    const float* bias = dir ? bb_ : bf_;
    float* C = hg + ((size_t)ks * 2 + dir) * NSEQ * G3H;

    float acc[2][2][4];
    #pragma unroll
    for (int i = 0; i < 2; i++)
        #pragma unroll
        for (int j = 0; j < 2; j++)
            #pragma unroll
            for (int r = 0; r < 4; r++) acc[i][j][r] = 0.f;

    float4 pa[2];
    uint4  pbh[2], pbl[2];
    #pragma unroll
    for (int i = 0; i < 2; i++) {
        int p = tid + i * 256, row = p >> 3, kc = (p & 7) * 4;
        pa[i]  = *(const float4*)(A  + (size_t)(m0 + row) * H_GRU + kbase + kc);
        pbh[i] = *(const uint4*)(Bh + (size_t)(n0t + row) * H_GRU + kbase + kc);
        pbl[i] = *(const uint4*)(Bl + (size_t)(n0t + row) * H_GRU + kbase + kc);
    }

    for (int k0 = 0; k0 < KSL; k0 += BK) {
        #pragma unroll
        for (int i = 0; i < 2; i++) {
            int p = tid + i * 256, row = p >> 3, kc = (p & 7) * 4;
            float av[4] = {pa[i].x, pa[i].y, pa[i].z, pa[i].w};
            #pragma unroll
            for (int e = 0; e < 4; e++) {
                uint32_t ah = f2tf32(av[e]);
                As_hi[row][kc + e] = ah;
                As_lo[row][kc + e] = f2tf32(av[e] - __uint_as_float(ah));
            }
            Bs_hi[row][kc+0] = pbh[i].x; Bs_hi[row][kc+1] = pbh[i].y;
            Bs_hi[row][kc+2] = pbh[i].z; Bs_hi[row][kc+3] = pbh[i].w;
            Bs_lo[row][kc+0] = pbl[i].x; Bs_lo[row][kc+1] = pbl[i].y;
            Bs_lo[row][kc+2] = pbl[i].z; Bs_lo[row][kc+3] = pbl[i].w;
        }
        __syncthreads();
        if (k0 + BK < KSL) {
            #pragma unroll
            for (int i = 0; i < 2; i++) {
                int p = tid + i * 256, row = p >> 3, kc = (p & 7) * 4;
                pa[i]  = *(const float4*)(A  + (size_t)(m0 + row) * H_GRU + kbase + k0 + BK + kc);
                pbh[i] = *(const uint4*)(Bh + (size_t)(n0t + row) * H_GRU + kbase + k0 + BK + kc);
                pbl[i] = *(const uint4*)(Bl + (size_t)(n0t + row) * H_GRU + kbase + k0 + BK + kc);
            }
        }
        #pragma unroll
        for (int kk = 0; kk < 4; kk++) {
            const int kb = kk * 8;
            uint32_t ah[2][4], al[2][4], bh[2][2], bl[2][2];
            #pragma unroll
            for (int i = 0; i < 2; i++) {
                int r0 = wm0 + i * 16 + g;
                ah[i][0] = As_hi[r0    ][kb + tg    ];
                ah[i][1] = As_hi[r0 + 8][kb + tg    ];
                ah[i][2] = As_hi[r0    ][kb + tg + 4];
                ah[i][3] = As_hi[r0 + 8][kb + tg + 4];
                al[i][0] = As_lo[r0    ][kb + tg    ];
                al[i][1] = As_lo[r0 + 8][kb + tg    ];
                al[i][2] = As_lo[r0    ][kb + tg + 4];
                al[i][3] = As_lo[r0 + 8][kb + tg + 4];
            }
            #pragma unroll
            for (int j = 0; j < 2; j++) {
                int nn = wn0 + j * 8 + g;
                bh[j][0] = Bs_hi[nn][kb + tg    ];
                bh[j][1] = Bs_hi[nn][kb + tg + 4];
                bl[j][0] = Bs_lo[nn][kb + tg    ];
                bl[j][1] = Bs_lo[nn][kb + tg + 4];
            }
            #pragma unroll
            for (int i = 0; i < 2; i++)
                #pragma unroll
                for (int j = 0; j < 2; j++) {
                    mma_tf32(acc[i][j], al[i][0], al[i][1], al[i][2], al[i][3],
                             bh[j][0], bh[j][1]);
                    mma_tf32(acc[i][j], ah[i][0], ah[i][1], ah[i][2], ah[i][3],
                             bl[j][0], bl[j][1]);
                    mma_tf32(acc[i][j], ah[i][0], ah[i][1], ah[i][2], ah[i][3],
                             bh[j][0], bh[j][1]);
                }
        }
        __syncthreads();
    }

    #pragma unroll
    for (int i = 0; i < 2; i++) {
        int row = m0 + wm0 + i * 16 + g;
        #pragma unroll
        for (int j = 0; j < 2; j++) {
            int col = n0t + wn0 + j * 8 + 2 * tg;
            float bv0 = 0.f, bv1 = 0.f;
            if (ks == 0) { bv0 = bias[col]; bv1 = bias[col + 1]; }
            float2 v0 = make_float2(acc[i][j][0] + bv0, acc[i][j][1] + bv1);
            float2 v1 = make_float2(acc[i][j][2] + bv0, acc[i][j][3] + bv1);
            *(float2*)(C + (size_t)row * G3H + col)       = v0;
            *(float2*)(C + (size_t)(row + 8) * G3H + col) = v1;
        }
    }
}

// ---------------- fp32 SIMT NT GEMM (small GEMMs) ----------------
template<int BM, int BN, int BK, int TM, int TN>
__global__ void __launch_bounds__((BM/TM)*(BN/TN))
gemm_nt(int M, int N, int K,
        const float* __restrict__ A0, const float* __restrict__ A1, int msplit, int lda,
        const float* __restrict__ B, int ldb,
        const float* __restrict__ bias,
        float* __restrict__ C, int ldc)
{
    constexpr int THREADS = (BM/TM)*(BN/TN);
    constexpr int KV = BK/4;
    __shared__ float Ast[BK][BM];
    __shared__ float Bst[BK][BN];
    const int tid = threadIdx.x;
    const int bm = blockIdx.y * BM;
    const int bn = blockIdx.x * BN;
    const int tx = tid % (BN/TN);
    const int ty = tid / (BN/TN);

    float acc[TM][TN];
    #pragma unroll
    for (int i = 0; i < TM; i++)
        #pragma unroll
        for (int j = 0; j < TN; j++) acc[i][j] = 0.f;

    for (int k0 = 0; k0 < K; k0 += BK) {
        #pragma unroll
        for (int p = tid; p < BM*KV; p += THREADS) {
            int row = p / KV;
            int kc  = (p % KV) * 4;
            int m = bm + row;
            float4 v = make_float4(0.f, 0.f, 0.f, 0.f);
            if (m < M) {
                const float* a = (m < msplit) ? (A0 + (size_t)m * lda)
                                              : (A1 + (size_t)(m - msplit) * lda);
                v = *(const float4*)(a + k0 + kc);
            }
            Ast[kc+0][row] = v.x; Ast[kc+1][row] = v.y;
            Ast[kc+2][row] = v.z; Ast[kc+3][row] = v.w;
        }
        #pragma unroll
        for (int p = tid; p < BN*KV; p += THREADS) {
            int row = p / KV;
            int kc  = (p % KV) * 4;
            int n = bn + row;
            float4 v = make_float4(0.f, 0.f, 0.f, 0.f);
            if (n < N) v = *(const float4*)(B + (size_t)n * ldb + k0 + kc);
            Bst[kc+0][row] = v.x; Bst[kc+1][row] = v.y;
            Bst[kc+2][row] = v.z; Bst[kc+3][row] = v.w;
        }
        __syncthreads();
        #pragma unroll
        for (int kk = 0; kk < BK; kk++) {
            float ra[TM], rb[TN];
            #pragma unroll
            for (int i = 0; i < TM; i += 4)
                *(float4*)&ra[i] = *(const float4*)&Ast[kk][ty*TM + i];
            #pragma unroll
            for (int j = 0; j < TN; j += 4)
                *(float4*)&rb[j] = *(const float4*)&Bst[kk][tx*TN + j];
            #pragma unroll
            for (int i = 0; i < TM; i++)
                #pragma unroll
                for (int j = 0; j < TN; j++)
                    acc[i][j] = fmaf(ra[i], rb[j], acc[i][j]);
        }
        __syncthreads();
    }
    #pragma unroll
    for (int i = 0; i < TM; i++) {
        int m = bm + ty*TM + i;
        if (m >= M) continue;
        #pragma unroll
        for (int j = 0; j < TN; j += 4) {
            int n = bn + tx*TN + j;
            float4 v;
            v.x = acc[i][j+0]; v.y = acc[i][j+1];
            v.z = acc[i][j+2]; v.w = acc[i][j+3];
            if (bias) { v.x += bias[n]; v.y += bias[n+1]; v.z += bias[n+2]; v.w += bias[n+3]; }
            *(float4*)(C + (size_t)m * ldc + n) = v;
        }
    }
}

// ---------------- misc kernels ----------------
__global__ void zero_kernel(float* p, int n) {
    int i = blockIdx.x * blockDim.x + threadIdx.x;
    if (i < n) p[i] = 0.f;
}

// one GRU timestep; sums the KSPLIT hg partial slices
__global__ void gru_step(const float* __restrict__ xg,
                         const float* __restrict__ hg_all,
                         float* __restrict__ h_all,
                         const float* __restrict__ vmask, const float* __restrict__ smask,
                         float* __restrict__ gru, int s)
{
    int idx = blockIdx.x * blockDim.x + threadIdx.x;
    if (idx >= 2 * NSEQ * (H_GRU / 4)) return;
    const int JW = H_GRU / 4;
    int dir = idx / (NSEQ * JW);
    int r = idx - dir * NSEQ * JW;
    int n = r / JW;
    int j4 = (r - n * JW) * 4;
    int t = dir ? (T_FRAMES - 1 - s) : s;

    size_t xo = ((size_t)n * T_FRAMES + t) * (2 * G3H) + (size_t)dir * G3H;
    float4 xr = *(const float4*)(xg + xo + j4);
    float4 xz = *(const float4*)(xg + xo + H_GRU + j4);
    float4 xn = *(const float4*)(xg + xo + 2*H_GRU + j4);

    float hrv[4] = {0.f, 0.f, 0.f, 0.f};
    float hzv[4] = {0.f, 0.f, 0.f, 0.f};
    float hnv[4] = {0.f, 0.f, 0.f, 0.f};
    #pragma unroll
    for (int ks = 0; ks < KSPLIT; ks++) {
        const float* hgp = hg_all + ((size_t)ks * 2 + dir) * NSEQ * G3H + (size_t)n * G3H;
        float4 a = *(const float4*)(hgp + j4);
        float4 b = *(const float4*)(hgp + H_GRU + j4);
        float4 c = *(const float4*)(hgp + 2*H_GRU + j4);
        hrv[0] += a.x; hrv[1] += a.y; hrv[2] += a.z; hrv[3] += a.w;
        hzv[0] += b.x; hzv[1] += b.y; hzv[2] += b.z; hzv[3] += b.w;
        hnv[0] += c.x; hnv[1] += c.y; hnv[2] += c.z; hnv[3] += c.w;
    }

    float* hp = h_all + (size_t)dir * NSEQ * H_GRU + (size_t)n * H_GRU + j4;
    float4 hold = *(float4*)hp;

    float mval = (n < NB) ? vmask[n * T_FRAMES + t]
                          : smask[(n - NB) * T_FRAMES + t];

    float xrv[4] = {xr.x, xr.y, xr.z, xr.w};
    float xzv[4] = {xz.x, xz.y, xz.z, xz.w};
    float xnv[4] = {xn.x, xn.y, xn.z, xn.w};
    float hov[4] = {hold.x, hold.y, hold.z, hold.w};
    float outv[4], gw[4];
    #pragma unroll
    for (int e = 0; e < 4; e++) {
        float rg = 1.f / (1.f + __expf(-(xrv[e] + hrv[e])));
        float zg = 1.f / (1.f + __expf(-(xzv[e] + hzv[e])));
        float ng = __tanhf(xnv[e] + rg * hnv[e]);
        float hv = (1.f - zg) * ng + zg * hov[e];
        outv[e] = hv;
        gw[e] = hv * mval;
    }
    *(float4*)hp = make_float4(outv[0], outv[1], outv[2], outv[3]);
    *(float4*)(gru + ((size_t)n * T_FRAMES + t) * C2H + dir * H_GRU + j4) =
        make_float4(gw[0], gw[1], gw[2], gw[3]);
}

__global__ void pool_origin(const float* __restrict__ gru,
                            const int* __restrict__ len, const int* __restrict__ slen,
                            const float* __restrict__ vorig, const float* __restrict__ sorig,
                            float* __restrict__ feat)
{
    int idx = blockIdx.x * blockDim.x + threadIdx.x;
    if (idx >= NSEQ * (C2H + D_IN)) return;
    int n = idx / (C2H + D_IN);
    int c = idx - n * (C2H + D_IN);
    if (c < C2H) {
        const float* g = gru + (size_t)n * T_FRAMES * C2H + c;
        float s = 0.f;
        #pragma unroll
        for (int t = 0; t < T_FRAMES; t++) s += g[(size_t)t * C2H];
        int L = (n < NB) ? len[n] : slen[n - NB];
        feat[(size_t)n * FEATD + c] = s / (float)L;
    } else {
        int cc = c - C2H;
        float v = (n < NB) ? vorig[(size_t)n * D_IN + cc]
                           : sorig[(size_t)(n - NB) * D_IN + cc];
        feat[(size_t)n * FEATD + (C2H + 4*512) + cc] = v;
    }
}

__global__ void pack_conv(const float* __restrict__ w2, const float* __restrict__ w3,
                          const float* __restrict__ w4, const float* __restrict__ w5,
                          float* __restrict__ Bc)
{
    int idx = blockIdx.x * blockDim.x + threadIdx.x;
    if (idx >= NCONV * C2H) return;
    int col = idx / C2H;
    int c = idx - col * C2H;
    int w, k, i; const float* src;
    if (col < 1024)      { w = 2; src = w2; int r = col;        k = r / 2; i = r - k*2; }
    else if (col < 2560) { w = 3; src = w3; int r = col - 1024; k = r / 3; i = r - k*3; }
    else if (col < 4608) { w = 4; src = w4; int r = col - 2560; k = r / 4; i = r - k*4; }
    else                 { w = 5; src = w5; int r = col - 4608; k = r / 5; i = r - k*5; }
    Bc[(size_t)col * C2H + c] = src[((size_t)k * C2H + c) * w + i];
}

__global__ void conv_reduce(const float* __restrict__ P,
                            const float* __restrict__ cb2, const float* __restrict__ cb3,
                            const float* __restrict__ cb4, const float* __restrict__ cb5,
                            float* __restrict__ feat)
{
    int idx = blockIdx.x * blockDim.x + threadIdx.x;
    if (idx >= NSEQ * 2048) return;
    int n = idx / 2048;
    int c = idx - n * 2048;
    int widx = c >> 9;
    int k = c & 511;
    int w = widx + 2;
    int base = (widx == 0) ? 0 : (widx == 1) ? 1024 : (widx == 2) ? 2560 : 4608;
    const float* cb = (widx == 0) ? cb2 : (widx == 1) ? cb3 : (widx == 2) ? cb4 : cb5;
    float bb = cb[k];
    const float* Pn = P + (size_t)n * T_FRAMES * NCONV + base + k * w;
    float best = 0.f;
    for (int tau = 0; tau < T_FRAMES + w - 1; tau++) {
        float y = bb;
        for (int i = 0; i < w; i++) {
            int t = tau + i - (w - 1);
            if (t >= 0 && t < T_FRAMES) y += Pn[(size_t)t * NCONV + i];
        }
        best = fmaxf(best, y);
    }
    feat[(size_t)n * FEATD + C2H + c] = best;
}

__global__ void attn_out(const float* __restrict__ feat, const float* __restrict__ q,
                         const float* __restrict__ kf, float* __restrict__ out)
{
    int b = blockIdx.x;
    int tid = threadIdx.x;
    __shared__ float logits[NS];
    __shared__ float wgt[NS];
    if (tid < 32 * NS) {
        int s = tid >> 5, lane = tid & 31;
        const float* kk = kf + (size_t)(b * NS + s) * 512;
        const float* qq = q + (size_t)b * 512;
        float sum = 0.f;
        for (int h = lane; h < 512; h += 32) sum += kk[h] * qq[h];
        #pragma unroll
        for (int o = 16; o; o >>= 1) sum += __shfl_down_sync(0xffffffffu, sum, o);
        if (lane == 0) logits[s] = sum;
    }
    __syncthreads();
    if (tid == 0) {
        float mx = fmaxf(fmaxf(logits[0], logits[1]), fmaxf(logits[2], logits[3]));
        float e0 = expf(logits[0]-mx), e1 = expf(logits[1]-mx);
        float e2 = expf(logits[2]-mx), e3 = expf(logits[3]-mx);
        float se = e0 + e1 + e2 + e3;
        wgt[0] = e0/se; wgt[1] = e1/se; wgt[2] = e2/se; wgt[3] = e3/se;
    }
    __syncthreads();
    float w0 = wgt[0], w1 = wgt[1], w2 = wgt[2], w3 = wgt[3];
    const float* f0 = feat + (size_t)b * FEATD;
    const float* s0 = feat + (size_t)(NB + b * NS) * FEATD;
    for (int f = tid; f < FEATD; f += blockDim.x) {
        out[(size_t)b * FEATD + f] = f0[f]
            + w0 * s0[f] + w1 * s0[FEATD + f]
            + w2 * s0[2*(size_t)FEATD + f] + w3 * s0[3*(size_t)FEATD + f];
    }
}

// ---------------- launch ----------------
extern "C" void kernel_launch(void* const* d_in, const int* in_sizes, int n_in,
                              void* d_out, int out_size)
{
    const float* videos   = (const float*)d_in[0];
    const float* vorigin  = (const float*)d_in[1];
    const int*   lengths  = (const int*)  d_in[2];
    const float* vmask    = (const float*)d_in[3];
    const float* svideos  = (const float*)d_in[4];
    const float* sorigin  = (const float*)d_in[5];
    const int*   slengths = (const int*)  d_in[6];
    const float* smask    = (const float*)d_in[7];
    const float* W_ih_f = (const float*)d_in[10];
    const float* W_hh_f = (const float*)d_in[11];
    const float* b_ih_f = (const float*)d_in[12];
    const float* b_hh_f = (const float*)d_in[13];
    const float* W_ih_b = (const float*)d_in[14];
    const float* W_hh_b = (const float*)d_in[15];
    const float* b_ih_b = (const float*)d_in[16];
    const float* b_hh_b = (const float*)d_in[17];
    const float* cw2 = (const float*)d_in[18]; const float* cb2 = (const float*)d_in[19];
    const float* cw3 = (const float*)d_in[20]; const float* cb3 = (const float*)d_in[21];
    const float* cw4 = (const float*)d_in[22]; const float* cb4 = (const float*)d_in[23];
    const float* cw5 = (const float*)d_in[24]; const float* cb5 = (const float*)d_in[25];
    const float* Wk = (const float*)d_in[26]; const float* bk = (const float*)d_in[27];
    const float* Wq = (const float*)d_in[28]; const float* bq = (const float*)d_in[29];
    float* out = (float*)d_out;

    float *p_xg, *p_h, *p_hg, *p_gru, *p_Bc, *p_P, *p_feat, *p_q, *p_k;
    uint32_t *p_Whi, *p_Wlo;
    cudaGetSymbolAddress((void**)&p_xg,   g_xg);
    cudaGetSymbolAddress((void**)&p_h,    g_h);
    cudaGetSymbolAddress((void**)&p_hg,   g_hg);
    cudaGetSymbolAddress((void**)&p_gru,  g_gru);
    cudaGetSymbolAddress((void**)&p_Bc,   g_Bc);
    cudaGetSymbolAddress((void**)&p_P,    g_P);
    cudaGetSymbolAddress((void**)&p_feat, g_feat);
    cudaGetSymbolAddress((void**)&p_q,    g_q);
    cudaGetSymbolAddress((void**)&p_k,    g_k);
    cudaGetSymbolAddress((void**)&p_Whi,  g_Whi);
    cudaGetSymbolAddress((void**)&p_Wlo,  g_Wlo);

    zero_kernel<<<(2*NSEQ*H_GRU + 255)/256, 256>>>(p_h, 2*NSEQ*H_GRU);
    pack_whh<<<(2*G3H*H_GRU + 255)/256, 256>>>(W_hh_f, W_hh_b, p_Whi, p_Wlo);

    // pack conv weights BEFORE the projection GEMM (reorder so ncu's fixed
    // sampling window lands on gemm_tf32 next round; no data dependency)
    pack_conv<<<(NCONV*C2H + 255)/256, 256>>>(cw2, cw3, cw4, cw5, p_Bc);

    // fused fwd+bwd input projection: [15360 x 2048] x [3072 x 2048]^T (tf32)
    gemm_tf32<<<dim3(2*G3H/128, M_ALL/128), 256>>>(M_ALL, 2*G3H, D_IN,
        videos, svideos, MAIN_ROWS, D_IN,
        W_ih_f, W_ih_b, G3H, D_IN,
        b_ih_f, b_ih_b, p_xg, 2*G3H);

    // GRU recurrence: split-K=4 hh GEMM (960 CTAs) + gate kernel summing partials
    for (int s = 0; s < T_FRAMES; s++) {
        gemm_hh_tf32<<<dim3(G3H/64, NSEQ/64, 2*KSPLIT), 256>>>(
            p_h, p_Whi, p_Wlo, b_hh_f, b_hh_b, p_hg);
        gru_step<<<(2*NSEQ*(H_GRU/4) + 255)/256, 256>>>(
            p_xg, p_hg, p_h, vmask, smask, p_gru, s);
    }

    pool_origin<<<(NSEQ*(C2H + D_IN) + 255)/256, 256>>>(
        p_gru, lengths, slengths, vorigin, sorigin, p_feat);

    // conv-as-GEMM: [15360 x 1024] x [7168 x 1024]^T (tf32)
    gemm_tf32<<<dim3(NCONV/128, M_ALL/128), 256>>>(M_ALL, NCONV, C2H,
        p_gru, p_gru, M_ALL, C2H,
        p_Bc, p_Bc, NCONV, C2H,
        nullptr, nullptr, p_P, NCONV);
    conv_reduce<<<(NSEQ*2048 + 255)/256, 256>>>(p_P, cb2, cb3, cb4, cb5, p_feat);

    // query / key projections (fp32)
    gemm_nt<64,64,16,4,4><<<dim3(512/64, 1), 256>>>(NB, 512, FEATD,
        p_feat, p_feat, NB, FEATD, Wq, FEATD, bq, p_q, 512);
    gemm_nt<64,64,16,4,4><<<dim3(512/64, 4), 256>>>(NB*NS, 512, FEATD,
        p_feat + (size_t)NB*FEATD, p_feat + (size_t)NB*FEATD, NB*NS, FEATD,
        Wk, FEATD, bk, p_k, 512);

    attn_out<<<NB, 256>>>(p_feat, p_q, p_k, out);
}